// round 14
// baseline (speedup 1.0000x reference)
#include <cuda_runtime.h>
#include <cuda_bf16.h>
#include <cuda_fp16.h>
#include <math.h>
#include <stdint.h>

// SimpleAttention B=4 S=2048 D=1024 fp32.
// QK: bf16 hi/lo 3-MMA fp32 emulation. PV: single fp16 MMA (err ~2e-4).
// R14: out_kernel split-K for qt>=8 writing unscaled partials to TWO scratch
// buffers; separate combine kernel (no inter-CTA sync anywhere). Diag-skip
// scores; half2 softmax. Single stream.

namespace {

constexpr int B = 4, S = 2048, D = 1024;
constexpr float NEGV = -1.0e9f;
constexpr int NQT = S / 128;                  // 16
constexpr int NTRI = NQT * (NQT + 1) / 2;     // 136

__device__ __align__(16) __nv_bfloat16 g_Xhi [(size_t)B * S * D];
__device__ __align__(16) __nv_bfloat16 g_Xlo [(size_t)B * S * D];
__device__ __align__(16) __half        g_XTh [(size_t)B * D * S];
__device__ __align__(16) float         g_S   [(size_t)B * S * S];
__device__ __align__(16) __half        g_E   [(size_t)B * S * S];
__device__ float g_inv[(size_t)B * S];
__device__ __align__(16) float g_PA[(size_t)B * S * D];   // split-K partial A
__device__ __align__(16) float g_PB[(size_t)B * S * D];   // split-K partial B

// ---------------- ptx helpers -------------------------------------------------
__device__ __forceinline__ uint32_t smem_u32(const void* p) {
    uint32_t a;
    asm("{ .reg .u64 t; cvta.to.shared.u64 t, %1; cvt.u32.u64 %0, t; }" : "=r"(a) : "l"(p));
    return a;
}
__device__ __forceinline__ void cpa16(uint32_t dst, const void* src) {
    asm volatile("cp.async.cg.shared.global [%0], [%1], 16;" :: "r"(dst), "l"(src) : "memory");
}
__device__ __forceinline__ void cpa_commit() {
    asm volatile("cp.async.commit_group;" ::: "memory");
}
template <int N> __device__ __forceinline__ void cpa_wait() {
    asm volatile("cp.async.wait_group %0;" :: "n"(N) : "memory");
}
__device__ __forceinline__ void ldm4(uint32_t* r, uint32_t addr) {
    asm volatile("ldmatrix.sync.aligned.m8n8.x4.shared.b16 {%0,%1,%2,%3}, [%4];"
                 : "=r"(r[0]), "=r"(r[1]), "=r"(r[2]), "=r"(r[3]) : "r"(addr));
}
__device__ __forceinline__ void mma_bf16(float* c, const uint32_t* a, const uint32_t* b) {
    asm volatile(
        "mma.sync.aligned.m16n8k16.row.col.f32.bf16.bf16.f32 "
        "{%0,%1,%2,%3}, {%4,%5,%6,%7}, {%8,%9}, {%0,%1,%2,%3};"
        : "+f"(c[0]), "+f"(c[1]), "+f"(c[2]), "+f"(c[3])
        : "r"(a[0]), "r"(a[1]), "r"(a[2]), "r"(a[3]), "r"(b[0]), "r"(b[1]));
}
__device__ __forceinline__ void mma_f16(float* c, const uint32_t* a, const uint32_t* b) {
    asm volatile(
        "mma.sync.aligned.m16n8k16.row.col.f32.f16.f16.f32 "
        "{%0,%1,%2,%3}, {%4,%5,%6,%7}, {%8,%9}, {%0,%1,%2,%3};"
        : "+f"(c[0]), "+f"(c[1]), "+f"(c[2]), "+f"(c[3])
        : "r"(a[0]), "r"(a[1]), "r"(a[2]), "r"(a[3]), "r"(b[0]), "r"(b[1]));
}

// ============== QK GEMM (bf16 3-MMA, 64B rows, 3 stages) ======================
constexpr int RB = 64;
constexpr int ARR_BYTES = 128 * RB;
constexpr int STAGE_BYTES = 4 * ARR_BYTES;    // 32768
constexpr int NSTAGE = 3;
constexpr int SMEM_QK = NSTAGE * STAGE_BYTES; // 98304

__device__ __forceinline__ uint32_t swz(int row, int seg) {
    return (uint32_t)(row * RB + ((seg ^ ((row >> 1) & 3)) << 4));
}

__device__ __forceinline__ void load_chunk_qk(
    uint32_t stage_base,
    const __nv_bfloat16* __restrict__ Ah, const __nv_bfloat16* __restrict__ Al,
    const __nv_bfloat16* __restrict__ Bh, const __nv_bfloat16* __restrict__ Bl,
    int t)
{
#pragma unroll
    for (int j = 0; j < 8; ++j) {
        const int s = t + j * 256;
        const int arr = s >> 9;
        const int rem = s & 511;
        const int row = rem >> 2;
        const int seg = rem & 3;
        const __nv_bfloat16* base = (arr == 0) ? Ah : (arr == 1) ? Al : (arr == 2) ? Bh : Bl;
        cpa16(stage_base + arr * ARR_BYTES + swz(row, seg),
              base + (size_t)row * D + seg * 8);
    }
}

__global__ void __launch_bounds__(256, 2) scores_kernel()
{
    extern __shared__ char sm[];
    const int idx = blockIdx.x;
    int qt = (int)((sqrtf(8.0f * (float)idx + 1.0f) - 1.0f) * 0.5f);
    while ((qt + 1) * (qt + 2) / 2 <= idx) ++qt;
    while (qt * (qt + 1) / 2 > idx) --qt;
    const int kt = idx - qt * (qt + 1) / 2;
    const int b = blockIdx.y;
    const int t = threadIdx.x;

    const __nv_bfloat16* Ah = g_Xhi + ((size_t)b * S + qt * 128) * D;
    const __nv_bfloat16* Al = g_Xlo + ((size_t)b * S + qt * 128) * D;
    const __nv_bfloat16* Bh = g_Xhi + ((size_t)b * S + kt * 128) * D;
    const __nv_bfloat16* Bl = g_Xlo + ((size_t)b * S + kt * 128) * D;
    float* out = g_S + ((size_t)b * S + qt * 128) * S + kt * 128;

    const uint32_t smb = smem_u32(sm);
    const int w = t >> 5, l = t & 31;
    const int wm = w >> 1, wn = w & 1;
    const int nch = D / 32;
    const bool active = !(qt == kt && wn == 1 && wm < 2);   // diag skip

    float acc[2][8][4];
#pragma unroll
    for (int i = 0; i < 2; ++i)
#pragma unroll
        for (int j = 0; j < 8; ++j)
#pragma unroll
            for (int k = 0; k < 4; ++k) acc[i][j][k] = 0.f;

    const int a_row = wm * 32 + (l & 15);
    const int a_seg = (l >> 4);
    const int b_row = wn * 64 + (l & 7) + (((l >> 4) & 1) << 3);
    const int b_seg = ((l >> 3) & 1);

    load_chunk_qk(smb, Ah, Al, Bh, Bl, t);
    cpa_commit();
    load_chunk_qk(smb + STAGE_BYTES, Ah + 32, Al + 32, Bh + 32, Bl + 32, t);
    cpa_commit();

    int stage = 0;
    for (int i = 0; i < nch; ++i) {
        if (i + 1 < nch) cpa_wait<1>();
        else             cpa_wait<0>();
        __syncthreads();
        if (i + 2 < nch) {
            int ns = stage + 2; if (ns >= NSTAGE) ns -= NSTAGE;
            load_chunk_qk(smb + ns * STAGE_BYTES,
                          Ah + (i + 2) * 32, Al + (i + 2) * 32,
                          Bh + (i + 2) * 32, Bl + (i + 2) * 32, t);
            cpa_commit();
        }
        const uint32_t sb = smb + stage * STAGE_BYTES;

        if (active) {
#pragma unroll
            for (int kk = 0; kk < 2; ++kk) {
                uint32_t ah[2][4], al[2][4];
#pragma unroll
                for (int f = 0; f < 2; ++f) {
                    const uint32_t ao = sb + swz(a_row + f * 16, kk * 2 + a_seg);
                    ldm4(ah[f], ao);
                    ldm4(al[f], ao + ARR_BYTES);
                }
#pragma unroll
                for (int p = 0; p < 4; ++p) {
                    const uint32_t bo = sb + 2 * ARR_BYTES + swz(b_row + p * 16, kk * 2 + b_seg);
                    uint32_t rh[4], rl[4];
                    ldm4(rh, bo);
                    ldm4(rl, bo + ARR_BYTES);
#pragma unroll
                    for (int h = 0; h < 2; ++h) {
                        const int nf = 2 * p + h;
                        mma_bf16(acc[0][nf], ah[0], rh + 2 * h);
                        mma_bf16(acc[1][nf], ah[1], rh + 2 * h);
                        mma_bf16(acc[0][nf], ah[0], rl + 2 * h);
                        mma_bf16(acc[1][nf], ah[1], rl + 2 * h);
                        mma_bf16(acc[0][nf], al[0], rh + 2 * h);
                        mma_bf16(acc[1][nf], al[1], rh + 2 * h);
                    }
                }
            }
        }
        if (++stage == NSTAGE) stage = 0;
    }

    if (active) {
        const int er = l >> 2, ec = (l & 3) << 1;
#pragma unroll
        for (int mf = 0; mf < 2; ++mf) {
            const int m0 = wm * 32 + mf * 16 + er;
#pragma unroll
            for (int nf = 0; nf < 8; ++nf) {
                const int n0 = wn * 64 + nf * 8 + ec;
                *reinterpret_cast<float2*>(out + (size_t)m0 * S + n0) =
                    make_float2(acc[mf][nf][0], acc[mf][nf][1]);
                *reinterpret_cast<float2*>(out + (size_t)(m0 + 8) * S + n0) =
                    make_float2(acc[mf][nf][2], acc[mf][nf][3]);
            }
        }
    }
}

// ============== PV GEMM (fp16 single-MMA, k-chunk 64, 3 stages) ================
constexpr int RB2 = 128;
constexpr int PV_ARR = 128 * RB2;
constexpr int PV_STAGE = 2 * PV_ARR;           // 32768
constexpr int PV_NSTAGE = 3;
constexpr int SMEM_PV = PV_NSTAGE * PV_STAGE;  // 98304

__device__ __forceinline__ uint32_t swz8(int row, int seg) {
    return (uint32_t)(row * RB2 + ((seg ^ (row & 7)) << 4));
}

__device__ __forceinline__ void load_chunk_pv(
    uint32_t stage_base,
    const __half* __restrict__ Ea, const __half* __restrict__ Va, int t)
{
#pragma unroll
    for (int j = 0; j < 8; ++j) {
        const int u = t + j * 256;
        const int arr = u >> 10;
        const int rem = u & 1023;
        const int row = rem >> 3;
        const int seg = rem & 7;
        const __half* base = arr ? Va : Ea;
        cpa16(stage_base + arr * PV_ARR + swz8(row, seg),
              base + (size_t)row * S + seg * 8);
    }
}

// Grid 768 linear:
//   bx in [0,512): heavy qt 15..8 split-K. qtIdx=bx>>6, r=bx&63, ks=r>>5,
//                  sub=r&31 (dt=sub&7, b=sub>>3). No cross-CTA sync.
//   bx in [512,768): light qt 7..0 full-K, direct scaled write.
__global__ void __launch_bounds__(256, 2) out_kernel(float* __restrict__ O)
{
    extern __shared__ char sm[];
    const int bx = blockIdx.x;
    int qt, ks, sub;
    if (bx < 512) { qt = NQT - 1 - (bx >> 6); const int r = bx & 63; ks = r >> 5; sub = r & 31; }
    else          { const int r = bx - 512; qt = 7 - (r >> 5); ks = -1; sub = r & 31; }
    const int dt = sub & 7;
    const int b = sub >> 3;
    const int t = threadIdx.x;

    const int nch  = (ks < 0) ? 2 * (qt + 1) : (qt + 1);
    const int koff = (ks == 1) ? (qt + 1) : 0;

    const __half* Ea = g_E + ((size_t)b * S + qt * 128) * S + koff * 64;
    const __half* Va = g_XTh + ((size_t)b * D + dt * 128) * S + koff * 64;
    const size_t obase = ((size_t)b * S + qt * 128) * D + dt * 128;

    const uint32_t smb = smem_u32(sm);
    const int w = t >> 5, l = t & 31;
    const int wm = w >> 1, wn = w & 1;

    float acc[2][8][4];
#pragma unroll
    for (int i = 0; i < 2; ++i)
#pragma unroll
        for (int j = 0; j < 8; ++j)
#pragma unroll
            for (int k = 0; k < 4; ++k) acc[i][j][k] = 0.f;

    const int a_row = wm * 32 + (l & 15);
    const int a_seg = (l >> 4);
    const int b_row = wn * 64 + (l & 7) + (((l >> 4) & 1) << 3);
    const int b_seg = ((l >> 3) & 1);

    load_chunk_pv(smb, Ea, Va, t);
    cpa_commit();
    if (nch > 1) {
        load_chunk_pv(smb + PV_STAGE, Ea + 64, Va + 64, t);
        cpa_commit();
    }

    int stage = 0;
    for (int i = 0; i < nch; ++i) {
        if (i + 1 < nch) cpa_wait<1>();
        else             cpa_wait<0>();
        __syncthreads();
        if (i + 2 < nch) {
            int ns = stage + 2; if (ns >= PV_NSTAGE) ns -= PV_NSTAGE;
            load_chunk_pv(smb + ns * PV_STAGE, Ea + (i + 2) * 64, Va + (i + 2) * 64, t);
            cpa_commit();
        }
        const uint32_t sb = smb + stage * PV_STAGE;

#pragma unroll
        for (int kk = 0; kk < 4; ++kk) {
            uint32_t af[2][4];
#pragma unroll
            for (int f = 0; f < 2; ++f)
                ldm4(af[f], sb + swz8(a_row + f * 16, kk * 2 + a_seg));
#pragma unroll
            for (int p = 0; p < 4; ++p) {
                uint32_t bf[4];
                ldm4(bf, sb + PV_ARR + swz8(b_row + p * 16, kk * 2 + b_seg));
                mma_f16(acc[0][2 * p],     af[0], bf + 0);
                mma_f16(acc[1][2 * p],     af[1], bf + 0);
                mma_f16(acc[0][2 * p + 1], af[0], bf + 2);
                mma_f16(acc[1][2 * p + 1], af[1], bf + 2);
            }
        }
        if (++stage == PV_NSTAGE) stage = 0;
    }

    const int er = l >> 2, ec = (l & 3) << 1;

    if (ks >= 0) {
        // unscaled partial to its own buffer (no sync needed)
        float* pp = (ks == 0 ? g_PA : g_PB) + obase;
#pragma unroll
        for (int mf = 0; mf < 2; ++mf) {
            const int m0 = wm * 32 + mf * 16 + er;
#pragma unroll
            for (int nf = 0; nf < 8; ++nf) {
                const int n0 = wn * 64 + nf * 8 + ec;
                *reinterpret_cast<float2*>(pp + (size_t)m0 * D + n0) =
                    make_float2(acc[mf][nf][0], acc[mf][nf][1]);
                *reinterpret_cast<float2*>(pp + (size_t)(m0 + 8) * D + n0) =
                    make_float2(acc[mf][nf][2], acc[mf][nf][3]);
            }
        }
        return;
    }

    // light: direct scaled write
    const float* invb = g_inv + (size_t)b * S + qt * 128;
    float* out = O + obase;
#pragma unroll
    for (int mf = 0; mf < 2; ++mf) {
        const int m0 = wm * 32 + mf * 16 + er;
        const float i0 = invb[m0], i1 = invb[m0 + 8];
#pragma unroll
        for (int nf = 0; nf < 8; ++nf) {
            const int n0 = wn * 64 + nf * 8 + ec;
            *reinterpret_cast<float2*>(out + (size_t)m0 * D + n0) =
                make_float2(acc[mf][nf][0] * i0, acc[mf][nf][1] * i0);
            *reinterpret_cast<float2*>(out + (size_t)(m0 + 8) * D + n0) =
                make_float2(acc[mf][nf][2] * i1, acc[mf][nf][3] * i1);
        }
    }
}

// ---------------- combine: O = (PA + PB) * inv over heavy rows ----------------
// Heavy rows: s in [S/2, S) for every batch. 4 float4 per thread.
__global__ void __launch_bounds__(256) combine_kernel(float* __restrict__ O)
{
    const int gid = blockIdx.x * 256 + threadIdx.x;
    const int D4 = D / 4;                     // 256 float4 per row
#pragma unroll
    for (int j = 0; j < 4; ++j) {
        const int u = gid * 4 + j;            // float4 index over heavy region
        const int per_b = (S / 2) * D4;       // 262144
        const int b = u / per_b;
        const int rem = u - b * per_b;
        const int srow = S / 2 + rem / D4;
        const int col = rem - (rem / D4) * D4;
        const size_t off = ((size_t)b * S + srow) * (size_t)D4 + col;
        const float4 a = reinterpret_cast<const float4*>(g_PA)[off];
        const float4 c = reinterpret_cast<const float4*>(g_PB)[off];
        const float inv = g_inv[(size_t)b * S + srow];
        reinterpret_cast<float4*>(O)[off] =
            make_float4((a.x + c.x) * inv, (a.y + c.y) * inv,
                        (a.z + c.z) * inv, (a.w + c.w) * inv);
    }
}

// ---------------- K1: split + fp16 transpose ----------------------------------
__global__ void __launch_bounds__(256) split_kernel(const float* __restrict__ X)
{
    __shared__ float tile[32][33];
    const int b = blockIdx.z;
    const int s0 = blockIdx.y * 32;
    const int d0 = blockIdx.x * 32;
    const int x = threadIdx.x, y0 = threadIdx.y;

#pragma unroll
    for (int yy = y0; yy < 32; yy += 8) {
        const size_t o = ((size_t)b * S + s0 + yy) * D + d0 + x;
        const float v = X[o];
        tile[yy][x] = v;
        const __nv_bfloat16 h = __float2bfloat16_rn(v);
        g_Xhi[o] = h;
        g_Xlo[o] = __float2bfloat16_rn(v - __bfloat162float(h));
    }
    __syncthreads();
#pragma unroll
    for (int yy = y0; yy < 32; yy += 8) {
        const float v = tile[x][yy];
        const size_t o = ((size_t)b * D + d0 + yy) * S + s0 + x;
        g_XTh[o] = __float2half_rn(v);
    }
}

// ---------------- K3: softmax -> unnormalized E fp16 + inv --------------------
__global__ void __launch_bounds__(256) softmax_kernel(const int* __restrict__ mask)
{
    __shared__ float row[S];
    __shared__ float red[8];
    const int q = blockIdx.x;
    const int b = blockIdx.y;
    const int t = threadIdx.x, w = t >> 5, lane = t & 31;
    const int L = q + 1;
    const int L4 = L & ~3;
    const int Kmax = ((q >> 7) + 1) << 7;

    const float* Srow = g_S + ((size_t)b * S + q) * S;
    const int* mb = mask + (size_t)b * S;

    float lm = -3.0e38f;
    for (int k = t * 4; k < L4; k += 1024) {
        const float4 v4 = *reinterpret_cast<const float4*>(Srow + k);
        const int4 m4 = *reinterpret_cast<const int4*>(mb + k);
        const float v0 = v4.x + (m4.x ? 0.0f : NEGV);
        const float v1 = v4.y + (m4.y ? 0.0f : NEGV);
        const float v2 = v4.z + (m4.z ? 0.0f : NEGV);
        const float v3 = v4.w + (m4.w ? 0.0f : NEGV);
        *reinterpret_cast<float4*>(row + k) = make_float4(v0, v1, v2, v3);
        lm = fmaxf(lm, fmaxf(fmaxf(v0, v1), fmaxf(v2, v3)));
    }
    for (int k = L4 + t; k < L; k += 256) {
        const float v = Srow[k] + (mb[k] ? 0.0f : NEGV);
        row[k] = v;
        lm = fmaxf(lm, v);
    }
#pragma unroll
    for (int d = 16; d > 0; d >>= 1) lm = fmaxf(lm, __shfl_xor_sync(0xffffffffu, lm, d));
    if (lane == 0) red[w] = lm;
    __syncthreads();
    const float m = fmaxf(fmaxf(fmaxf(red[0], red[1]), fmaxf(red[2], red[3])),
                          fmaxf(fmaxf(red[4], red[5]), fmaxf(red[6], red[7])));

    __half* Eh = g_E + ((size_t)b * S + q) * S;
    float ls = 0.0f;
    for (int k = t * 4; k < L4; k += 1024) {
        const float4 v = *reinterpret_cast<const float4*>(row + k);
        const float e0 = __expf(v.x - m), e1 = __expf(v.y - m);
        const float e2 = __expf(v.z - m), e3 = __expf(v.w - m);
        *reinterpret_cast<__half2*>(Eh + k)     = __floats2half2_rn(e0, e1);
        *reinterpret_cast<__half2*>(Eh + k + 2) = __floats2half2_rn(e2, e3);
        ls += (e0 + e1) + (e2 + e3);
    }
    for (int k = L4 + t; k < L; k += 256) {
        const float e = __expf(row[k] - m);
        Eh[k] = __float2half_rn(e);
        ls += e;
    }
#pragma unroll
    for (int d = 16; d > 0; d >>= 1) ls += __shfl_xor_sync(0xffffffffu, ls, d);
    __syncthreads();
    if (lane == 0) red[w] = ls;
    __syncthreads();
    const float sum = (red[0] + red[1]) + (red[2] + red[3]) +
                      (red[4] + red[5]) + (red[6] + red[7]);
    if (t == 0) g_inv[(size_t)b * S + q] = 1.0f / sum;

    const __half z = __float2half_rn(0.0f);
    for (int k = L + t; k < Kmax; k += 256) Eh[k] = z;
}

} // namespace

extern "C" void kernel_launch(void* const* d_in, const int* in_sizes, int n_in,
                              void* d_out, int out_size)
{
    const float* X = (const float*)d_in[0];
    const int* mask = (const int*)d_in[1];
    float* O = (float*)d_out;

    cudaFuncSetAttribute(scores_kernel, cudaFuncAttributeMaxDynamicSharedMemorySize, SMEM_QK);
    cudaFuncSetAttribute(out_kernel, cudaFuncAttributeMaxDynamicSharedMemorySize, SMEM_PV);

    split_kernel<<<dim3(D / 32, S / 32, B), dim3(32, 8)>>>(X);
    scores_kernel<<<dim3(NTRI, B), 256, SMEM_QK>>>();
    softmax_kernel<<<dim3(S, B), 256>>>(mask);
    out_kernel<<<dim3(768), 256, SMEM_PV>>>(O);
    // heavy region: B * (S/2) * D / 4 float4 = 1048576; 4 per thread -> 1024 CTAs
    combine_kernel<<<dim3(1024), 256>>>(O);
}

// round 15
// speedup vs baseline: 1.0644x; 1.0644x over previous
#include <cuda_runtime.h>
#include <cuda_bf16.h>
#include <cuda_fp16.h>
#include <math.h>
#include <stdint.h>

// SimpleAttention B=4 S=2048 D=1024 fp32.
// QK: bf16 hi/lo 3-MMA fp32 emulation (3-stage cp.async pipeline).
// PV: single fp16 MMA on unnormalized E (err ~2e-4), LPT-ordered grid.
// R15: consolidation — R10 single-stream skeleton + diag-skip scores +
// half2 softmax. No split-K, no streams, no flags.

namespace {

constexpr int B = 4, S = 2048, D = 1024;
constexpr float NEGV = -1.0e9f;
constexpr int NQT = S / 128;                  // 16
constexpr int NTRI = NQT * (NQT + 1) / 2;     // 136

__device__ __align__(16) __nv_bfloat16 g_Xhi [(size_t)B * S * D];
__device__ __align__(16) __nv_bfloat16 g_Xlo [(size_t)B * S * D];
__device__ __align__(16) __half        g_XTh [(size_t)B * D * S];
__device__ __align__(16) float         g_S   [(size_t)B * S * S];
__device__ __align__(16) __half        g_E   [(size_t)B * S * S];
__device__ float g_inv[(size_t)B * S];

// ---------------- ptx helpers -------------------------------------------------
__device__ __forceinline__ uint32_t smem_u32(const void* p) {
    uint32_t a;
    asm("{ .reg .u64 t; cvta.to.shared.u64 t, %1; cvt.u32.u64 %0, t; }" : "=r"(a) : "l"(p));
    return a;
}
__device__ __forceinline__ void cpa16(uint32_t dst, const void* src) {
    asm volatile("cp.async.cg.shared.global [%0], [%1], 16;" :: "r"(dst), "l"(src) : "memory");
}
__device__ __forceinline__ void cpa_commit() {
    asm volatile("cp.async.commit_group;" ::: "memory");
}
template <int N> __device__ __forceinline__ void cpa_wait() {
    asm volatile("cp.async.wait_group %0;" :: "n"(N) : "memory");
}
__device__ __forceinline__ void ldm4(uint32_t* r, uint32_t addr) {
    asm volatile("ldmatrix.sync.aligned.m8n8.x4.shared.b16 {%0,%1,%2,%3}, [%4];"
                 : "=r"(r[0]), "=r"(r[1]), "=r"(r[2]), "=r"(r[3]) : "r"(addr));
}
__device__ __forceinline__ void mma_bf16(float* c, const uint32_t* a, const uint32_t* b) {
    asm volatile(
        "mma.sync.aligned.m16n8k16.row.col.f32.bf16.bf16.f32 "
        "{%0,%1,%2,%3}, {%4,%5,%6,%7}, {%8,%9}, {%0,%1,%2,%3};"
        : "+f"(c[0]), "+f"(c[1]), "+f"(c[2]), "+f"(c[3])
        : "r"(a[0]), "r"(a[1]), "r"(a[2]), "r"(a[3]), "r"(b[0]), "r"(b[1]));
}
__device__ __forceinline__ void mma_f16(float* c, const uint32_t* a, const uint32_t* b) {
    asm volatile(
        "mma.sync.aligned.m16n8k16.row.col.f32.f16.f16.f32 "
        "{%0,%1,%2,%3}, {%4,%5,%6,%7}, {%8,%9}, {%0,%1,%2,%3};"
        : "+f"(c[0]), "+f"(c[1]), "+f"(c[2]), "+f"(c[3])
        : "r"(a[0]), "r"(a[1]), "r"(a[2]), "r"(a[3]), "r"(b[0]), "r"(b[1]));
}

// ============== QK GEMM (bf16 3-MMA, 64B rows, 3 stages) ======================
constexpr int RB = 64;
constexpr int ARR_BYTES = 128 * RB;           // 8192
constexpr int STAGE_BYTES = 4 * ARR_BYTES;    // 32768
constexpr int NSTAGE = 3;
constexpr int SMEM_QK = NSTAGE * STAGE_BYTES; // 98304

__device__ __forceinline__ uint32_t swz(int row, int seg) {
    return (uint32_t)(row * RB + ((seg ^ ((row >> 1) & 3)) << 4));
}

__device__ __forceinline__ void load_chunk_qk(
    uint32_t stage_base,
    const __nv_bfloat16* __restrict__ Ah, const __nv_bfloat16* __restrict__ Al,
    const __nv_bfloat16* __restrict__ Bh, const __nv_bfloat16* __restrict__ Bl,
    int t)
{
#pragma unroll
    for (int j = 0; j < 8; ++j) {
        const int s = t + j * 256;
        const int arr = s >> 9;
        const int rem = s & 511;
        const int row = rem >> 2;
        const int seg = rem & 3;
        const __nv_bfloat16* base = (arr == 0) ? Ah : (arr == 1) ? Al : (arr == 2) ? Bh : Bl;
        cpa16(stage_base + arr * ARR_BYTES + swz(row, seg),
              base + (size_t)row * D + seg * 8);
    }
}

__global__ void __launch_bounds__(256, 2) scores_kernel()
{
    extern __shared__ char sm[];
    const int idx = blockIdx.x;
    int qt = (int)((sqrtf(8.0f * (float)idx + 1.0f) - 1.0f) * 0.5f);
    while ((qt + 1) * (qt + 2) / 2 <= idx) ++qt;
    while (qt * (qt + 1) / 2 > idx) --qt;
    const int kt = idx - qt * (qt + 1) / 2;
    const int b = blockIdx.y;
    const int t = threadIdx.x;

    const __nv_bfloat16* Ah = g_Xhi + ((size_t)b * S + qt * 128) * D;
    const __nv_bfloat16* Al = g_Xlo + ((size_t)b * S + qt * 128) * D;
    const __nv_bfloat16* Bh = g_Xhi + ((size_t)b * S + kt * 128) * D;
    const __nv_bfloat16* Bl = g_Xlo + ((size_t)b * S + kt * 128) * D;
    float* out = g_S + ((size_t)b * S + qt * 128) * S + kt * 128;

    const uint32_t smb = smem_u32(sm);
    const int w = t >> 5, l = t & 31;
    const int wm = w >> 1, wn = w & 1;
    const int nch = D / 32;
    // diagonal tiles: warps (wm<2, wn=1) cover only strictly-upper outputs
    const bool active = !(qt == kt && wn == 1 && wm < 2);

    float acc[2][8][4];
#pragma unroll
    for (int i = 0; i < 2; ++i)
#pragma unroll
        for (int j = 0; j < 8; ++j)
#pragma unroll
            for (int k = 0; k < 4; ++k) acc[i][j][k] = 0.f;

    const int a_row = wm * 32 + (l & 15);
    const int a_seg = (l >> 4);
    const int b_row = wn * 64 + (l & 7) + (((l >> 4) & 1) << 3);
    const int b_seg = ((l >> 3) & 1);

    load_chunk_qk(smb, Ah, Al, Bh, Bl, t);
    cpa_commit();
    load_chunk_qk(smb + STAGE_BYTES, Ah + 32, Al + 32, Bh + 32, Bl + 32, t);
    cpa_commit();

    int stage = 0;
    for (int i = 0; i < nch; ++i) {
        if (i + 1 < nch) cpa_wait<1>();
        else             cpa_wait<0>();
        __syncthreads();
        if (i + 2 < nch) {
            int ns = stage + 2; if (ns >= NSTAGE) ns -= NSTAGE;
            load_chunk_qk(smb + ns * STAGE_BYTES,
                          Ah + (i + 2) * 32, Al + (i + 2) * 32,
                          Bh + (i + 2) * 32, Bl + (i + 2) * 32, t);
            cpa_commit();
        }
        const uint32_t sb = smb + stage * STAGE_BYTES;

        if (active) {
#pragma unroll
            for (int kk = 0; kk < 2; ++kk) {
                uint32_t ah[2][4], al[2][4];
#pragma unroll
                for (int f = 0; f < 2; ++f) {
                    const uint32_t ao = sb + swz(a_row + f * 16, kk * 2 + a_seg);
                    ldm4(ah[f], ao);
                    ldm4(al[f], ao + ARR_BYTES);
                }
#pragma unroll
                for (int p = 0; p < 4; ++p) {
                    const uint32_t bo = sb + 2 * ARR_BYTES + swz(b_row + p * 16, kk * 2 + b_seg);
                    uint32_t rh[4], rl[4];
                    ldm4(rh, bo);
                    ldm4(rl, bo + ARR_BYTES);
#pragma unroll
                    for (int h = 0; h < 2; ++h) {
                        const int nf = 2 * p + h;
                        mma_bf16(acc[0][nf], ah[0], rh + 2 * h);
                        mma_bf16(acc[1][nf], ah[1], rh + 2 * h);
                        mma_bf16(acc[0][nf], ah[0], rl + 2 * h);
                        mma_bf16(acc[1][nf], ah[1], rl + 2 * h);
                        mma_bf16(acc[0][nf], al[0], rh + 2 * h);
                        mma_bf16(acc[1][nf], al[1], rh + 2 * h);
                    }
                }
            }
        }
        if (++stage == NSTAGE) stage = 0;
    }

    if (active) {
        const int er = l >> 2, ec = (l & 3) << 1;
#pragma unroll
        for (int mf = 0; mf < 2; ++mf) {
            const int m0 = wm * 32 + mf * 16 + er;
#pragma unroll
            for (int nf = 0; nf < 8; ++nf) {
                const int n0 = wn * 64 + nf * 8 + ec;
                *reinterpret_cast<float2*>(out + (size_t)m0 * S + n0) =
                    make_float2(acc[mf][nf][0], acc[mf][nf][1]);
                *reinterpret_cast<float2*>(out + (size_t)(m0 + 8) * S + n0) =
                    make_float2(acc[mf][nf][2], acc[mf][nf][3]);
            }
        }
    }
}

// ============== PV GEMM (fp16 single-MMA, k-chunk 64, 3 stages) ================
constexpr int RB2 = 128;
constexpr int PV_ARR = 128 * RB2;              // 16384
constexpr int PV_STAGE = 2 * PV_ARR;           // 32768
constexpr int PV_NSTAGE = 3;
constexpr int SMEM_PV = PV_NSTAGE * PV_STAGE;  // 98304

__device__ __forceinline__ uint32_t swz8(int row, int seg) {
    return (uint32_t)(row * RB2 + ((seg ^ (row & 7)) << 4));
}

__device__ __forceinline__ void load_chunk_pv(
    uint32_t stage_base,
    const __half* __restrict__ Ea, const __half* __restrict__ Va, int t)
{
#pragma unroll
    for (int j = 0; j < 8; ++j) {
        const int u = t + j * 256;
        const int arr = u >> 10;
        const int rem = u & 1023;
        const int row = rem >> 3;
        const int seg = rem & 7;
        const __half* base = arr ? Va : Ea;
        cpa16(stage_base + arr * PV_ARR + swz8(row, seg),
              base + (size_t)row * S + seg * 8);
    }
}

// Linear grid 512, LPT: qt descends every 32 CTAs (8 dt x 4 b).
__global__ void __launch_bounds__(256, 2) out_kernel(float* __restrict__ O)
{
    extern __shared__ char sm[];
    const int bx = blockIdx.x;
    const int qt = NQT - 1 - (bx >> 5);
    const int sub = bx & 31;
    const int dt = sub & 7;
    const int b = sub >> 3;
    const int t = threadIdx.x;

    const __half* Ea = g_E + ((size_t)b * S + qt * 128) * S;
    const __half* Va = g_XTh + ((size_t)b * D + dt * 128) * S;
    float* out = O + ((size_t)b * S + qt * 128) * D + dt * 128;
    const int nch = 2 * (qt + 1);

    const uint32_t smb = smem_u32(sm);
    const int w = t >> 5, l = t & 31;
    const int wm = w >> 1, wn = w & 1;

    float acc[2][8][4];
#pragma unroll
    for (int i = 0; i < 2; ++i)
#pragma unroll
        for (int j = 0; j < 8; ++j)
#pragma unroll
            for (int k = 0; k < 4; ++k) acc[i][j][k] = 0.f;

    const int a_row = wm * 32 + (l & 15);
    const int a_seg = (l >> 4);
    const int b_row = wn * 64 + (l & 7) + (((l >> 4) & 1) << 3);
    const int b_seg = ((l >> 3) & 1);

    load_chunk_pv(smb, Ea, Va, t);
    cpa_commit();
    if (nch > 1) {
        load_chunk_pv(smb + PV_STAGE, Ea + 64, Va + 64, t);
        cpa_commit();
    }

    int stage = 0;
    for (int i = 0; i < nch; ++i) {
        if (i + 1 < nch) cpa_wait<1>();
        else             cpa_wait<0>();
        __syncthreads();
        if (i + 2 < nch) {
            int ns = stage + 2; if (ns >= PV_NSTAGE) ns -= PV_NSTAGE;
            load_chunk_pv(smb + ns * PV_STAGE, Ea + (i + 2) * 64, Va + (i + 2) * 64, t);
            cpa_commit();
        }
        const uint32_t sb = smb + stage * PV_STAGE;

#pragma unroll
        for (int kk = 0; kk < 4; ++kk) {
            uint32_t af[2][4];
#pragma unroll
            for (int f = 0; f < 2; ++f)
                ldm4(af[f], sb + swz8(a_row + f * 16, kk * 2 + a_seg));
#pragma unroll
            for (int p = 0; p < 4; ++p) {
                uint32_t bf[4];
                ldm4(bf, sb + PV_ARR + swz8(b_row + p * 16, kk * 2 + b_seg));
                mma_f16(acc[0][2 * p],     af[0], bf + 0);
                mma_f16(acc[1][2 * p],     af[1], bf + 0);
                mma_f16(acc[0][2 * p + 1], af[0], bf + 2);
                mma_f16(acc[1][2 * p + 1], af[1], bf + 2);
            }
        }
        if (++stage == PV_NSTAGE) stage = 0;
    }

    const float* invb = g_inv + (size_t)b * S + qt * 128;
    const int er = l >> 2, ec = (l & 3) << 1;
#pragma unroll
    for (int mf = 0; mf < 2; ++mf) {
        const int m0 = wm * 32 + mf * 16 + er;
        const float i0 = invb[m0], i1 = invb[m0 + 8];
#pragma unroll
        for (int nf = 0; nf < 8; ++nf) {
            const int n0 = wn * 64 + nf * 8 + ec;
            *reinterpret_cast<float2*>(out + (size_t)m0 * D + n0) =
                make_float2(acc[mf][nf][0] * i0, acc[mf][nf][1] * i0);
            *reinterpret_cast<float2*>(out + (size_t)(m0 + 8) * D + n0) =
                make_float2(acc[mf][nf][2] * i1, acc[mf][nf][3] * i1);
        }
    }
}

// ---------------- K1: split + fp16 transpose ----------------------------------
__global__ void __launch_bounds__(256) split_kernel(const float* __restrict__ X)
{
    __shared__ float tile[32][33];
    const int b = blockIdx.z;
    const int s0 = blockIdx.y * 32;
    const int d0 = blockIdx.x * 32;
    const int x = threadIdx.x, y0 = threadIdx.y;

#pragma unroll
    for (int yy = y0; yy < 32; yy += 8) {
        const size_t o = ((size_t)b * S + s0 + yy) * D + d0 + x;
        const float v = X[o];
        tile[yy][x] = v;
        const __nv_bfloat16 h = __float2bfloat16_rn(v);
        g_Xhi[o] = h;
        g_Xlo[o] = __float2bfloat16_rn(v - __bfloat162float(h));
    }
    __syncthreads();
#pragma unroll
    for (int yy = y0; yy < 32; yy += 8) {
        const float v = tile[x][yy];
        const size_t o = ((size_t)b * D + d0 + yy) * S + s0 + x;
        g_XTh[o] = __float2half_rn(v);
    }
}

// ---------------- K3: softmax -> unnormalized E fp16 + inv (half2) ------------
__global__ void __launch_bounds__(256) softmax_kernel(const int* __restrict__ mask)
{
    __shared__ float row[S];
    __shared__ float red[8];
    const int q = blockIdx.x;
    const int b = blockIdx.y;
    const int t = threadIdx.x, w = t >> 5, lane = t & 31;
    const int L = q + 1;
    const int L4 = L & ~3;
    const int Kmax = ((q >> 7) + 1) << 7;

    const float* Srow = g_S + ((size_t)b * S + q) * S;
    const int* mb = mask + (size_t)b * S;

    float lm = -3.0e38f;
    for (int k = t * 4; k < L4; k += 1024) {
        const float4 v4 = *reinterpret_cast<const float4*>(Srow + k);
        const int4 m4 = *reinterpret_cast<const int4*>(mb + k);
        const float v0 = v4.x + (m4.x ? 0.0f : NEGV);
        const float v1 = v4.y + (m4.y ? 0.0f : NEGV);
        const float v2 = v4.z + (m4.z ? 0.0f : NEGV);
        const float v3 = v4.w + (m4.w ? 0.0f : NEGV);
        *reinterpret_cast<float4*>(row + k) = make_float4(v0, v1, v2, v3);
        lm = fmaxf(lm, fmaxf(fmaxf(v0, v1), fmaxf(v2, v3)));
    }
    for (int k = L4 + t; k < L; k += 256) {
        const float v = Srow[k] + (mb[k] ? 0.0f : NEGV);
        row[k] = v;
        lm = fmaxf(lm, v);
    }
#pragma unroll
    for (int d = 16; d > 0; d >>= 1) lm = fmaxf(lm, __shfl_xor_sync(0xffffffffu, lm, d));
    if (lane == 0) red[w] = lm;
    __syncthreads();
    const float m = fmaxf(fmaxf(fmaxf(red[0], red[1]), fmaxf(red[2], red[3])),
                          fmaxf(fmaxf(red[4], red[5]), fmaxf(red[6], red[7])));

    __half* Eh = g_E + ((size_t)b * S + q) * S;
    float ls = 0.0f;
    for (int k = t * 4; k < L4; k += 1024) {
        const float4 v = *reinterpret_cast<const float4*>(row + k);
        const float e0 = __expf(v.x - m), e1 = __expf(v.y - m);
        const float e2 = __expf(v.z - m), e3 = __expf(v.w - m);
        *reinterpret_cast<__half2*>(Eh + k)     = __floats2half2_rn(e0, e1);
        *reinterpret_cast<__half2*>(Eh + k + 2) = __floats2half2_rn(e2, e3);
        ls += (e0 + e1) + (e2 + e3);
    }
    for (int k = L4 + t; k < L; k += 256) {
        const float e = __expf(row[k] - m);
        Eh[k] = __float2half_rn(e);
        ls += e;
    }
#pragma unroll
    for (int d = 16; d > 0; d >>= 1) ls += __shfl_xor_sync(0xffffffffu, ls, d);
    __syncthreads();
    if (lane == 0) red[w] = ls;
    __syncthreads();
    const float sum = (red[0] + red[1]) + (red[2] + red[3]) +
                      (red[4] + red[5]) + (red[6] + red[7]);
    if (t == 0) g_inv[(size_t)b * S + q] = 1.0f / sum;

    const __half z = __float2half_rn(0.0f);
    for (int k = L + t; k < Kmax; k += 256) Eh[k] = z;
}

} // namespace

extern "C" void kernel_launch(void* const* d_in, const int* in_sizes, int n_in,
                              void* d_out, int out_size)
{
    const float* X = (const float*)d_in[0];
    const int* mask = (const int*)d_in[1];
    float* O = (float*)d_out;

    cudaFuncSetAttribute(scores_kernel, cudaFuncAttributeMaxDynamicSharedMemorySize, SMEM_QK);
    cudaFuncSetAttribute(out_kernel, cudaFuncAttributeMaxDynamicSharedMemorySize, SMEM_PV);

    split_kernel<<<dim3(D / 32, S / 32, B), dim3(32, 8)>>>(X);
    scores_kernel<<<dim3(NTRI, B), 256, SMEM_QK>>>();
    softmax_kernel<<<dim3(S, B), 256>>>(mask);
    out_kernel<<<dim3(NQT * 32), 256, SMEM_PV>>>(O);
}